// round 1
// baseline (speedup 1.0000x reference)
#include <cuda_runtime.h>
#include <cuda_bf16.h>
#include <math.h>

// ---------------------------------------------------------------------------
// Problem constants
// ---------------------------------------------------------------------------
#define BATCH   8192
#define DIN     5169      // 1723*3
#define DH      1024
#define DOUT    226
#define EPS     1e-5f

// ---------------------------------------------------------------------------
// Device scratch (no allocations allowed)
// ---------------------------------------------------------------------------
__device__ float g_Y[BATCH * DH];     // pre-BN gemm output
__device__ float g_H[BATCH * DH];     // residual stream
__device__ float g_T[BATCH * DH];     // temp stream
__device__ float g_O[BATCH * DOUT];   // final linear output
__device__ float g_sum[DH];
__device__ float g_sumsq[DH];
__device__ float g_a[DH];             // BN folded scale
__device__ float g_c[DH];             // BN folded shift

// ---------------------------------------------------------------------------
// SGEMM: C = A(MxK) * B(KxN) + bias(N), row-major, fp32
// 128x128 block tile, 8x8 per thread, BK=8, double buffered
// ---------------------------------------------------------------------------
#define BM 128
#define BN 128
#define BK 8
#define TM 8
#define TN 8
#define APAD 4

__global__ __launch_bounds__(256, 2) void sgemm_bias(
    const float* __restrict__ A, const float* __restrict__ B,
    const float* __restrict__ bias, float* __restrict__ C,
    int M, int N, int K)
{
    __shared__ float As[2][BK][BM + APAD];
    __shared__ float Bs[2][BK][BN];

    const int tid  = threadIdx.x;
    const int row0 = blockIdx.y * BM;
    const int col0 = blockIdx.x * BN;

    const int tRow = (tid >> 4) * TM;      // 16 thread rows
    const int tCol = (tid & 15) * TN;      // 16 thread cols

    float acc[TM][TN];
#pragma unroll
    for (int i = 0; i < TM; i++)
#pragma unroll
        for (int j = 0; j < TN; j++) acc[i][j] = 0.f;

    const int numTiles = (K + BK - 1) / BK;

    // ---- preload tile 0 ----
#pragma unroll
    for (int i = 0; i < 4; i++) {
        int idx = i * 256 + tid;
        int r = idx >> 3, k = idx & 7;
        As[0][k][r] = (k < K) ? A[(size_t)(row0 + r) * K + k] : 0.f;
    }
#pragma unroll
    for (int i = 0; i < 4; i++) {
        int idx = i * 256 + tid;
        int k = idx >> 7, c = idx & 127;
        float v = 0.f;
        if (k < K && (col0 + c) < N) v = B[(size_t)k * N + col0 + c];
        Bs[0][k][c] = v;
    }
    __syncthreads();

    int buf = 0;
    float aReg[4], bReg[4];

    for (int t = 0; t < numTiles; t++) {
        const int kNext = (t + 1) * BK;
        if (t + 1 < numTiles) {
#pragma unroll
            for (int i = 0; i < 4; i++) {
                int idx = i * 256 + tid;
                int r = idx >> 3, k = idx & 7;
                int gk = kNext + k;
                aReg[i] = (gk < K) ? A[(size_t)(row0 + r) * K + gk] : 0.f;
            }
#pragma unroll
            for (int i = 0; i < 4; i++) {
                int idx = i * 256 + tid;
                int k = idx >> 7, c = idx & 127;
                int gk = kNext + k;
                bReg[i] = (gk < K && (col0 + c) < N) ? B[(size_t)gk * N + col0 + c] : 0.f;
            }
        }

        // ---- compute on current buffer ----
#pragma unroll
        for (int k = 0; k < BK; k++) {
            float ra[TM], rb[TN];
            const float4* a4 = reinterpret_cast<const float4*>(&As[buf][k][tRow]);
            const float4* b4 = reinterpret_cast<const float4*>(&Bs[buf][k][tCol]);
            float4 va0 = a4[0], va1 = a4[1];
            float4 vb0 = b4[0], vb1 = b4[1];
            ra[0]=va0.x; ra[1]=va0.y; ra[2]=va0.z; ra[3]=va0.w;
            ra[4]=va1.x; ra[5]=va1.y; ra[6]=va1.z; ra[7]=va1.w;
            rb[0]=vb0.x; rb[1]=vb0.y; rb[2]=vb0.z; rb[3]=vb0.w;
            rb[4]=vb1.x; rb[5]=vb1.y; rb[6]=vb1.z; rb[7]=vb1.w;
#pragma unroll
            for (int i = 0; i < TM; i++)
#pragma unroll
                for (int j = 0; j < TN; j++)
                    acc[i][j] = fmaf(ra[i], rb[j], acc[i][j]);
        }

        if (t + 1 < numTiles) {
            int nbuf = buf ^ 1;
#pragma unroll
            for (int i = 0; i < 4; i++) {
                int idx = i * 256 + tid;
                As[nbuf][idx & 7][idx >> 3] = aReg[i];
            }
#pragma unroll
            for (int i = 0; i < 4; i++) {
                int idx = i * 256 + tid;
                Bs[nbuf][idx >> 7][idx & 127] = bReg[i];
            }
            __syncthreads();
            buf = nbuf;
        }
    }

    // ---- epilogue ----
#pragma unroll
    for (int i = 0; i < TM; i++) {
        int r = row0 + tRow + i;
#pragma unroll
        for (int j = 0; j < TN; j++) {
            int c = col0 + tCol + j;
            if (c < N) C[(size_t)r * N + c] = acc[i][j] + bias[c];
        }
    }
}

// ---------------------------------------------------------------------------
// BN stats over batch (columns of Y, 8192 x 1024)
// ---------------------------------------------------------------------------
__global__ void zero_stats() {
    int i = threadIdx.x;
    g_sum[i] = 0.f;
    g_sumsq[i] = 0.f;
}

__global__ void colstats(const float* __restrict__ Y) {
    // grid (32, 32), block (32, 8)
    const int col = blockIdx.x * 32 + threadIdx.x;
    const int rowsPerBlock = BATCH / gridDim.y;
    const int r0 = blockIdx.y * rowsPerBlock;
    float s = 0.f, q = 0.f;
    for (int r = r0 + threadIdx.y; r < r0 + rowsPerBlock; r += 8) {
        float v = Y[(size_t)r * DH + col];
        s += v;
        q = fmaf(v, v, q);
    }
    __shared__ float ss[8][32];
    __shared__ float sq[8][32];
    ss[threadIdx.y][threadIdx.x] = s;
    sq[threadIdx.y][threadIdx.x] = q;
    __syncthreads();
    if (threadIdx.y == 0) {
        float S = 0.f, Q = 0.f;
#pragma unroll
        for (int i = 0; i < 8; i++) { S += ss[i][threadIdx.x]; Q += sq[i][threadIdx.x]; }
        atomicAdd(&g_sum[col], S);
        atomicAdd(&g_sumsq[col], Q);
    }
}

__global__ void finalize_bn(const float* __restrict__ g, const float* __restrict__ be) {
    int c = blockIdx.x * blockDim.x + threadIdx.x;
    if (c >= DH) return;
    const float invM = 1.f / (float)BATCH;
    float mean = g_sum[c] * invM;
    float var  = g_sumsq[c] * invM - mean * mean;
    float a = g[c] * rsqrtf(var + EPS);
    g_a[c] = a;
    g_c[c] = be[c] - a * mean;
}

// D = relu( (res? res : 0) + a*Y + c ), vectorized float4
__global__ void apply_bn(const float4* __restrict__ Y4,
                         const float4* __restrict__ R4,
                         float4* __restrict__ D4,
                         int has_res)
{
    int i = blockIdx.x * blockDim.x + threadIdx.x;
    if (i >= BATCH * DH / 4) return;
    int c4 = i & 255;                               // DH/4 = 256
    float4 a = reinterpret_cast<const float4*>(g_a)[c4];
    float4 c = reinterpret_cast<const float4*>(g_c)[c4];
    float4 y = Y4[i];
    float4 r = make_float4(0.f, 0.f, 0.f, 0.f);
    if (has_res) r = R4[i];
    float4 o;
    o.x = fmaxf(0.f, fmaf(a.x, y.x, c.x) + r.x);
    o.y = fmaxf(0.f, fmaf(a.y, y.y, c.y) + r.y);
    o.z = fmaxf(0.f, fmaf(a.z, y.z, c.z) + r.z);
    o.w = fmaxf(0.f, fmaf(a.w, y.w, c.w) + r.w);
    D4[i] = o;
}

// ---------------------------------------------------------------------------
// Polar decomposition of 3x3 (== U*Vh from SVD), times sign(det(A))
// Determinant-scaled Newton: X <- 0.5*(g*X + (1/g)*X^{-T}),  g = |det|^{-1/3}
// ---------------------------------------------------------------------------
__device__ __forceinline__ void cof3(const float* X, float* C) {
    C[0] = X[4]*X[8] - X[5]*X[7];
    C[1] = X[5]*X[6] - X[3]*X[8];
    C[2] = X[3]*X[7] - X[4]*X[6];
    C[3] = X[2]*X[7] - X[1]*X[8];
    C[4] = X[0]*X[8] - X[2]*X[6];
    C[5] = X[1]*X[6] - X[0]*X[7];
    C[6] = X[1]*X[5] - X[2]*X[4];
    C[7] = X[2]*X[3] - X[0]*X[5];
    C[8] = X[0]*X[4] - X[1]*X[3];
}

__global__ void polar_kernel(const float* __restrict__ O, float* __restrict__ out) {
    int n = blockIdx.x * blockDim.x + threadIdx.x;
    if (n >= BATCH * 24) return;
    int r = n / 24, m = n % 24;
    const float* src = O + (size_t)r * DOUT + m * 9;
    float X[9];
#pragma unroll
    for (int i = 0; i < 9; i++) X[i] = src[i];

    float C[9];
    cof3(X, C);
    float det0 = X[0]*C[0] + X[1]*C[1] + X[2]*C[2];
    float sgn = (det0 >= 0.f) ? 1.f : -1.f;

    // scale so spectral norm <= 1
    float fro = 0.f;
#pragma unroll
    for (int i = 0; i < 9; i++) fro = fmaf(X[i], X[i], fro);
    float inv = rsqrtf(fmaxf(fro, 1e-30f));
#pragma unroll
    for (int i = 0; i < 9; i++) X[i] *= inv;

#pragma unroll
    for (int it = 0; it < 12; it++) {
        cof3(X, C);
        float det = X[0]*C[0] + X[1]*C[1] + X[2]*C[2];
        float adet = fabsf(det);
        if (adet < 1e-30f) break;
        float gscale = rcbrtf(adet);              // |det|^(-1/3)
        float invdet = 1.f / det;
        float ig = 0.5f * invdet / gscale;
        float hg = 0.5f * gscale;
#pragma unroll
        for (int i = 0; i < 9; i++) X[i] = hg * X[i] + ig * C[i];
    }

    float* dst = out + (size_t)n * 9;
#pragma unroll
    for (int i = 0; i < 9; i++) dst[i] = X[i] * sgn;
}

__global__ void betas_kernel(const float* __restrict__ O, float* __restrict__ out) {
    int i = blockIdx.x * blockDim.x + threadIdx.x;
    if (i >= BATCH * 10) return;
    int r = i / 10, j = i % 10;
    out[(size_t)BATCH * 216 + i] = O[(size_t)r * DOUT + 216 + j];
}

// ---------------------------------------------------------------------------
// Launch
// ---------------------------------------------------------------------------
extern "C" void kernel_launch(void* const* d_in, const int* in_sizes, int n_in,
                              void* d_out, int out_size)
{
    const float* V   = (const float*)d_in[0];
    const float* W0  = (const float*)d_in[1];
    const float* b0  = (const float*)d_in[2];
    const float* g0  = (const float*)d_in[3];
    const float* be0 = (const float*)d_in[4];
    const float* W1a = (const float*)d_in[5];
    const float* b1a = (const float*)d_in[6];
    const float* g1a = (const float*)d_in[7];
    const float* be1a= (const float*)d_in[8];
    const float* W1b = (const float*)d_in[9];
    const float* b1b = (const float*)d_in[10];
    const float* g1b = (const float*)d_in[11];
    const float* be1b= (const float*)d_in[12];
    const float* W2a = (const float*)d_in[13];
    const float* b2a = (const float*)d_in[14];
    const float* g2a = (const float*)d_in[15];
    const float* be2a= (const float*)d_in[16];
    const float* W2b = (const float*)d_in[17];
    const float* b2b = (const float*)d_in[18];
    const float* g2b = (const float*)d_in[19];
    const float* be2b= (const float*)d_in[20];
    const float* W3  = (const float*)d_in[21];
    const float* b3  = (const float*)d_in[22];

    float *Y, *H, *T, *O;
    cudaGetSymbolAddress((void**)&Y, g_Y);
    cudaGetSymbolAddress((void**)&H, g_H);
    cudaGetSymbolAddress((void**)&T, g_T);
    cudaGetSymbolAddress((void**)&O, g_O);

    const dim3 gemmGrid(DH / BN, BATCH / BM);       // (8, 64)
    const dim3 gemmGrid3((DOUT + BN - 1) / BN, BATCH / BM);
    const dim3 statGrid(32, 32), statBlk(32, 8);
    const int applyBlocks = (BATCH * DH / 4 + 255) / 256;

    auto bn_stats = [&](const float* g, const float* be) {
        zero_stats<<<1, DH>>>();
        colstats<<<statGrid, statBlk>>>(Y);
        finalize_bn<<<DH / 256, 256>>>(g, be);
    };

    // layer 0: h = relu(bn(x @ W0 + b0))
    sgemm_bias<<<gemmGrid, 256>>>(V, W0, b0, Y, BATCH, DH, DIN);
    bn_stats(g0, be0);
    apply_bn<<<applyBlocks, 256>>>((const float4*)Y, nullptr, (float4*)H, 0);

    // block 1
    sgemm_bias<<<gemmGrid, 256>>>(H, W1a, b1a, Y, BATCH, DH, DH);
    bn_stats(g1a, be1a);
    apply_bn<<<applyBlocks, 256>>>((const float4*)Y, nullptr, (float4*)T, 0);
    sgemm_bias<<<gemmGrid, 256>>>(T, W1b, b1b, Y, BATCH, DH, DH);
    bn_stats(g1b, be1b);
    apply_bn<<<applyBlocks, 256>>>((const float4*)Y, (const float4*)H, (float4*)H, 1);

    // block 2
    sgemm_bias<<<gemmGrid, 256>>>(H, W2a, b2a, Y, BATCH, DH, DH);
    bn_stats(g2a, be2a);
    apply_bn<<<applyBlocks, 256>>>((const float4*)Y, nullptr, (float4*)T, 0);
    sgemm_bias<<<gemmGrid, 256>>>(T, W2b, b2b, Y, BATCH, DH, DH);
    bn_stats(g2b, be2b);
    apply_bn<<<applyBlocks, 256>>>((const float4*)Y, (const float4*)H, (float4*)H, 1);

    // head
    sgemm_bias<<<gemmGrid3, 256>>>(H, W3, b3, O, BATCH, DOUT, DH);

    // polar(out[:, :216]) * sign(det), betas passthrough
    polar_kernel<<<(BATCH * 24 + 255) / 256, 256>>>(O, (float*)d_out);
    betas_kernel<<<(BATCH * 10 + 255) / 256, 256>>>(O, (float*)d_out);
}

// round 5
// speedup vs baseline: 1.8104x; 1.8104x over previous
#include <cuda_runtime.h>
#include <cuda_bf16.h>
#include <math.h>
#include <stdint.h>

// ---------------------------------------------------------------------------
// Problem constants
// ---------------------------------------------------------------------------
#define BATCH   8192
#define DIN     5169      // 1723*3
#define DINP    5184      // padded to 64
#define DH      1024
#define DOUT    226
#define DOUTP   256
#define EPS     1e-5f

// GEMM tiling (mma.sync path): block 128x128, 512 threads, warp tile 32x32
#define BM      128
#define BN      128
#define BK      64
#define NTHREADS 512
#define OFF_A1  0
#define OFF_A2  16384
#define OFF_A3  32768
#define OFF_B1  49152
#define OFF_B2  65536
#define OFF_B3  81920
#define STAGE   98304
#define SMEM_REQ (2*STAGE)

__device__ __forceinline__ uint32_t smem_u32(const void* p) {
    uint32_t a;
    asm("{ .reg .u64 t; cvta.to.shared.u64 t, %1; cvt.u32.u64 %0, t; }" : "=r"(a) : "l"(p));
    return a;
}

#define CPA16(dst, src) asm volatile("cp.async.cg.shared.global [%0], [%1], 16;" :: "r"(dst), "l"(src) : "memory")
#define CP_COMMIT() asm volatile("cp.async.commit_group;" ::: "memory")
#define CP_WAIT1()  asm volatile("cp.async.wait_group 1;" ::: "memory")
#define CP_WAIT0()  asm volatile("cp.async.wait_group 0;" ::: "memory")

#define LDSM4(r, addr) \
    asm volatile("ldmatrix.sync.aligned.m8n8.x4.shared.b16 {%0,%1,%2,%3}, [%4];" \
        : "=r"((r)[0]), "=r"((r)[1]), "=r"((r)[2]), "=r"((r)[3]) : "r"(addr))

#define MMA16816(c, a, b) \
    asm volatile("mma.sync.aligned.m16n8k16.row.col.f32.bf16.bf16.f32 " \
        "{%0,%1,%2,%3}, {%4,%5,%6,%7}, {%8,%9}, {%0,%1,%2,%3};" \
        : "+f"((c)[0]), "+f"((c)[1]), "+f"((c)[2]), "+f"((c)[3]) \
        : "r"((a)[0]), "r"((a)[1]), "r"((a)[2]), "r"((a)[3]), \
          "r"((b)[0]), "r"((b)[1]))

// ---------------------------------------------------------------------------
// Device scratch
// ---------------------------------------------------------------------------
__device__ float g_Y[BATCH * DH];
__device__ float g_H[BATCH * DH];
__device__ float g_O[BATCH * DOUT];
__device__ float g_sum[DH];
__device__ float g_sumsq[DH];
__device__ float g_a[DH];
__device__ float g_c[DH];

// 3-way bf16 splits for activations
__device__ __nv_bfloat16 g_A01[BATCH * DINP];
__device__ __nv_bfloat16 g_A02[BATCH * DINP];
__device__ __nv_bfloat16 g_A03[BATCH * DINP];
__device__ __nv_bfloat16 g_H1[BATCH * DH];
__device__ __nv_bfloat16 g_H2[BATCH * DH];
__device__ __nv_bfloat16 g_H3[BATCH * DH];
__device__ __nv_bfloat16 g_T1[BATCH * DH];
__device__ __nv_bfloat16 g_T2[BATCH * DH];
__device__ __nv_bfloat16 g_T3[BATCH * DH];

// 3-way bf16 splits for weights (transposed [N][K])
__device__ __nv_bfloat16 g_W0s[3][DH * DINP];
__device__ __nv_bfloat16 g_W1as[3][DH * DH];
__device__ __nv_bfloat16 g_W1bs[3][DH * DH];
__device__ __nv_bfloat16 g_W2as[3][DH * DH];
__device__ __nv_bfloat16 g_W2bs[3][DH * DH];
__device__ __nv_bfloat16 g_W3s[3][DOUTP * DH];

// ---------------------------------------------------------------------------
// Prep: transpose+split weights  W[K][N] fp32 -> s1/s2/s3 [Npad][Kpad] bf16
// ---------------------------------------------------------------------------
__global__ void split_transpose(const float* __restrict__ W,
                                __nv_bfloat16* __restrict__ s1,
                                __nv_bfloat16* __restrict__ s2,
                                __nv_bfloat16* __restrict__ s3,
                                int K, int N, int Kpad, int Npad)
{
    __shared__ float sh[32][33];
    int k0 = blockIdx.x * 32, n0 = blockIdx.y * 32;
    int tx = threadIdx.x, ty = threadIdx.y;
    int k = k0 + ty, n = n0 + tx;
    sh[ty][tx] = (k < K && n < N) ? W[(size_t)k * N + n] : 0.f;
    __syncthreads();
    int no = n0 + ty, ko = k0 + tx;
    if (no < Npad && ko < Kpad) {
        float v = sh[tx][ty];
        __nv_bfloat16 h1 = __float2bfloat16(v);
        float r1 = v - __bfloat162float(h1);
        __nv_bfloat16 h2 = __float2bfloat16(r1);
        float r2 = r1 - __bfloat162float(h2);
        size_t idx = (size_t)no * Kpad + ko;
        s1[idx] = h1;
        s2[idx] = h2;
        s3[idx] = __float2bfloat16(r2);
    }
}

// Prep: split activations with K padding (row-major, no transpose)
__global__ void split_pad_rows(const float* __restrict__ src,
                               __nv_bfloat16* __restrict__ s1,
                               __nv_bfloat16* __restrict__ s2,
                               __nv_bfloat16* __restrict__ s3,
                               int cols, int colsPad, int total)
{
    int idx = blockIdx.x * blockDim.x + threadIdx.x;
    if (idx >= total) return;
    int r = idx / colsPad, c = idx - r * colsPad;
    float v = (c < cols) ? src[(size_t)r * cols + c] : 0.f;
    __nv_bfloat16 h1 = __float2bfloat16(v);
    float r1 = v - __bfloat162float(h1);
    __nv_bfloat16 h2 = __float2bfloat16(r1);
    float r2 = r1 - __bfloat162float(h2);
    s1[idx] = h1;
    s2[idx] = h2;
    s3[idx] = __float2bfloat16(r2);
}

// ---------------------------------------------------------------------------
// mma.sync 3-split bf16 GEMM (fp32-accurate, split accumulators):
//   C[M][ldC] = A(M x Kpad) * B^T(Npad x Kpad) + bias
// main acc: a1b1.  corr acc: a2b1, a3b1, a1b2, a2b2, a1b3.
// Grid (Npad/BN, M/BM), 512 threads (16 warps), warp tile 32x32.
// ---------------------------------------------------------------------------
__device__ __forceinline__ void prefetch_stage(
    uint32_t s0,
    const __nv_bfloat16* __restrict__ A1, const __nv_bfloat16* __restrict__ A2,
    const __nv_bfloat16* __restrict__ A3,
    const __nv_bfloat16* __restrict__ B1, const __nv_bfloat16* __restrict__ B2,
    const __nv_bfloat16* __restrict__ B3,
    int row0, int col0, size_t Kpad, size_t kb, int tid)
{
#pragma unroll
    for (int i = 0; i < 2; i++) {
        int idx = i * NTHREADS + tid;
        int r = idx >> 3, c8 = idx & 7;
        uint32_t dst = (uint32_t)(r * 128 + ((c8 ^ (r & 7)) << 4));
        size_t g = (size_t)(row0 + r) * Kpad + kb + (size_t)c8 * 8;
        CPA16(s0 + OFF_A1 + dst, A1 + g);
        CPA16(s0 + OFF_A2 + dst, A2 + g);
        CPA16(s0 + OFF_A3 + dst, A3 + g);
    }
#pragma unroll
    for (int i = 0; i < 2; i++) {
        int idx = i * NTHREADS + tid;
        int r = idx >> 3, c8 = idx & 7;
        uint32_t dst = (uint32_t)(r * 128 + ((c8 ^ (r & 7)) << 4));
        size_t g = (size_t)(col0 + r) * Kpad + kb + (size_t)c8 * 8;
        CPA16(s0 + OFF_B1 + dst, B1 + g);
        CPA16(s0 + OFF_B2 + dst, B2 + g);
        CPA16(s0 + OFF_B3 + dst, B3 + g);
    }
    CP_COMMIT();
}

__global__ void __launch_bounds__(NTHREADS, 1) gemm_mma_split3(
    const __nv_bfloat16* __restrict__ A1, const __nv_bfloat16* __restrict__ A2,
    const __nv_bfloat16* __restrict__ A3,
    const __nv_bfloat16* __restrict__ B1, const __nv_bfloat16* __restrict__ B2,
    const __nv_bfloat16* __restrict__ B3,
    const float* __restrict__ bias, float* __restrict__ C,
    int Kpad, int Nreal, int ldC)
{
    extern __shared__ char smraw[];
    const uint32_t sb = smem_u32(smraw);

    const int tid = threadIdx.x, wid = tid >> 5, lane = tid & 31;
    const int row0 = blockIdx.y * BM;
    const int col0 = blockIdx.x * BN;
    const int wm = (wid >> 2) * 32;        // warp m-offset: 4 groups of 32
    const int wn = (wid & 3) * 32;         // warp n-offset: 4 groups of 32
    const int T = Kpad / BK;

    float am[2][4][4];     // main accumulator (a1*b1)
    float ac[2][4][4];     // correction accumulator (5 small terms)
#pragma unroll
    for (int i = 0; i < 2; i++)
#pragma unroll
        for (int j = 0; j < 4; j++)
#pragma unroll
            for (int v = 0; v < 4; v++) { am[i][j][v] = 0.f; ac[i][j][v] = 0.f; }

    const int la_r  = (lane & 7) + (lane & 8);            // A row within 16
    const int la_kh = (lane & 16) ? 8 : 0;                // A k-half
    const int lb_r  = (lane & 7) + ((lane & 16) ? 8 : 0); // B n-row within 16
    const int lb_kh = (lane & 8) ? 8 : 0;                 // B k-half

    prefetch_stage(sb, A1, A2, A3, B1, B2, B3, row0, col0, (size_t)Kpad, 0, tid);

    for (int t = 0; t < T; t++) {
        if (t + 1 < T) {
            prefetch_stage(sb + ((t + 1) & 1) * STAGE, A1, A2, A3, B1, B2, B3,
                           row0, col0, (size_t)Kpad, (size_t)(t + 1) * BK, tid);
            CP_WAIT1();
        } else {
            CP_WAIT0();
        }
        __syncthreads();

        const uint32_t s0 = sb + (t & 1) * STAGE;
#pragma unroll
        for (int ks = 0; ks < 4; ks++) {
            // hoist A splits: 2 m-tiles x 3 splits = 6 LDSM4 (24 regs)
            uint32_t a1[2][4], a2[2][4], a3[2][4];
#pragma unroll
            for (int i = 0; i < 2; i++) {
                int r = wm + 16 * i + la_r;
                int k = ks * 16 + la_kh;
                uint32_t addr = s0 + OFF_A1 + r * 128 + ((((k >> 3) ^ r) & 7) << 4);
                LDSM4(a1[i], addr);
                LDSM4(a2[i], addr + (OFF_A2 - OFF_A1));
                LDSM4(a3[i], addr + (OFF_A3 - OFF_A1));
            }
            const int rB = wn + lb_r;
            const int kB = ks * 16 + lb_kh;
            const uint32_t baddr0 = s0 + OFF_B1 + rB * 128 + ((((kB >> 3) ^ rB) & 7) << 4);
            const uint32_t baddr1 = s0 + OFF_B1 + (rB + 16) * 128 + ((((kB >> 3) ^ (rB + 16)) & 7) << 4);

            // ---- B split 1: a1b1 -> main; a2b1, a3b1 -> corr ----
            {
                uint32_t b[4][2], q[4];
                LDSM4(q, baddr0);
                b[0][0]=q[0]; b[0][1]=q[1]; b[1][0]=q[2]; b[1][1]=q[3];
                LDSM4(q, baddr1);
                b[2][0]=q[0]; b[2][1]=q[1]; b[3][0]=q[2]; b[3][1]=q[3];
#pragma unroll
                for (int i = 0; i < 2; i++)
#pragma unroll
                    for (int j = 0; j < 4; j++) {
                        MMA16816(am[i][j], a1[i], b[j]);
                        MMA16816(ac[i][j], a2[i], b[j]);
                        MMA16816(ac[i][j], a3[i], b[j]);
                    }
            }
            // ---- B split 2: a1b2, a2b2 -> corr ----
            {
                uint32_t b[4][2], q[4];
                LDSM4(q, baddr0 + (OFF_B2 - OFF_B1));
                b[0][0]=q[0]; b[0][1]=q[1]; b[1][0]=q[2]; b[1][1]=q[3];
                LDSM4(q, baddr1 + (OFF_B2 - OFF_B1));
                b[2][0]=q[0]; b[2][1]=q[1]; b[3][0]=q[2]; b[3][1]=q[3];
#pragma unroll
                for (int i = 0; i < 2; i++)
#pragma unroll
                    for (int j = 0; j < 4; j++) {
                        MMA16816(ac[i][j], a1[i], b[j]);
                        MMA16816(ac[i][j], a2[i], b[j]);
                    }
            }
            // ---- B split 3: a1b3 -> corr ----
            {
                uint32_t b[4][2], q[4];
                LDSM4(q, baddr0 + (OFF_B3 - OFF_B1));
                b[0][0]=q[0]; b[0][1]=q[1]; b[1][0]=q[2]; b[1][1]=q[3];
                LDSM4(q, baddr1 + (OFF_B3 - OFF_B1));
                b[2][0]=q[0]; b[2][1]=q[1]; b[3][0]=q[2]; b[3][1]=q[3];
#pragma unroll
                for (int i = 0; i < 2; i++)
#pragma unroll
                    for (int j = 0; j < 4; j++)
                        MMA16816(ac[i][j], a1[i], b[j]);
            }
        }
        __syncthreads();
    }

    // epilogue: combine accumulators, add bias, store
    const int gid = lane >> 2, tig = lane & 3;
#pragma unroll
    for (int i = 0; i < 2; i++) {
        int r = row0 + wm + 16 * i + gid;
#pragma unroll
        for (int j = 0; j < 4; j++) {
            int cc = col0 + wn + 8 * j + tig * 2;
            if (cc < Nreal) {
                float b0 = bias[cc], b1 = bias[cc + 1];
                float2 v0 = make_float2(am[i][j][0] + ac[i][j][0] + b0,
                                        am[i][j][1] + ac[i][j][1] + b1);
                float2 v1 = make_float2(am[i][j][2] + ac[i][j][2] + b0,
                                        am[i][j][3] + ac[i][j][3] + b1);
                *reinterpret_cast<float2*>(C + (size_t)r * ldC + cc) = v0;
                *reinterpret_cast<float2*>(C + (size_t)(r + 8) * ldC + cc) = v1;
            }
        }
    }
}

// ---------------------------------------------------------------------------
// BN stats over batch
// ---------------------------------------------------------------------------
__global__ void zero_stats() {
    int i = threadIdx.x;
    g_sum[i] = 0.f;
    g_sumsq[i] = 0.f;
}

__global__ void colstats(const float* __restrict__ Y) {
    const int col = blockIdx.x * 32 + threadIdx.x;
    const int rowsPerBlock = BATCH / gridDim.y;
    const int r0 = blockIdx.y * rowsPerBlock;
    float s = 0.f, q = 0.f;
    for (int r = r0 + threadIdx.y; r < r0 + rowsPerBlock; r += 8) {
        float v = Y[(size_t)r * DH + col];
        s += v;
        q = fmaf(v, v, q);
    }
    __shared__ float ss[8][32];
    __shared__ float sq[8][32];
    ss[threadIdx.y][threadIdx.x] = s;
    sq[threadIdx.y][threadIdx.x] = q;
    __syncthreads();
    if (threadIdx.y == 0) {
        float S = 0.f, Q = 0.f;
#pragma unroll
        for (int i = 0; i < 8; i++) { S += ss[i][threadIdx.x]; Q += sq[i][threadIdx.x]; }
        atomicAdd(&g_sum[col], S);
        atomicAdd(&g_sumsq[col], Q);
    }
}

__global__ void finalize_bn(const float* __restrict__ g, const float* __restrict__ be) {
    int c = blockIdx.x * blockDim.x + threadIdx.x;
    if (c >= DH) return;
    const float invM = 1.f / (float)BATCH;
    float mean = g_sum[c] * invM;
    float var  = g_sumsq[c] * invM - mean * mean;
    float a = g[c] * rsqrtf(var + EPS);
    g_a[c] = a;
    g_c[c] = be[c] - a * mean;
}

// D = relu( res + a*Y + c ), write fp32 (optional) + 3-way bf16 splits
__global__ void apply_bn_split(const float4* __restrict__ Y4,
                               const float4* __restrict__ R4,
                               float4* __restrict__ H4,
                               uint2* __restrict__ o1,
                               uint2* __restrict__ o2,
                               uint2* __restrict__ o3,
                               int has_res, int write_f32)
{
    int i = blockIdx.x * blockDim.x + threadIdx.x;
    if (i >= BATCH * DH / 4) return;
    int c4 = i & 255;
    float4 a = reinterpret_cast<const float4*>(g_a)[c4];
    float4 c = reinterpret_cast<const float4*>(g_c)[c4];
    float4 y = Y4[i];
    float4 r = make_float4(0.f, 0.f, 0.f, 0.f);
    if (has_res) r = R4[i];
    float o[4];
    o[0] = fmaxf(0.f, fmaf(a.x, y.x, c.x) + r.x);
    o[1] = fmaxf(0.f, fmaf(a.y, y.y, c.y) + r.y);
    o[2] = fmaxf(0.f, fmaf(a.z, y.z, c.z) + r.z);
    o[3] = fmaxf(0.f, fmaf(a.w, y.w, c.w) + r.w);
    if (write_f32) H4[i] = make_float4(o[0], o[1], o[2], o[3]);

    union { __nv_bfloat162 b[2]; uint2 u; } p1, p2, p3;
#pragma unroll
    for (int v = 0; v < 4; v++) {
        __nv_bfloat16 h1 = __float2bfloat16(o[v]);
        float r1 = o[v] - __bfloat162float(h1);
        __nv_bfloat16 h2 = __float2bfloat16(r1);
        float r2 = r1 - __bfloat162float(h2);
        __nv_bfloat16 h3 = __float2bfloat16(r2);
        reinterpret_cast<__nv_bfloat16*>(p1.b)[v] = h1;
        reinterpret_cast<__nv_bfloat16*>(p2.b)[v] = h2;
        reinterpret_cast<__nv_bfloat16*>(p3.b)[v] = h3;
    }
    o1[i] = p1.u;
    o2[i] = p2.u;
    o3[i] = p3.u;
}

// ---------------------------------------------------------------------------
// Polar decomposition of 3x3 (== U*Vh), times sign(det)
// ---------------------------------------------------------------------------
__device__ __forceinline__ void cof3(const float* X, float* C) {
    C[0] = X[4]*X[8] - X[5]*X[7];
    C[1] = X[5]*X[6] - X[3]*X[8];
    C[2] = X[3]*X[7] - X[4]*X[6];
    C[3] = X[2]*X[7] - X[1]*X[8];
    C[4] = X[0]*X[8] - X[2]*X[6];
    C[5] = X[1]*X[6] - X[0]*X[7];
    C[6] = X[1]*X[5] - X[2]*X[4];
    C[7] = X[2]*X[3] - X[0]*X[5];
    C[8] = X[0]*X[4] - X[1]*X[3];
}

__global__ void polar_kernel(const float* __restrict__ O, float* __restrict__ out) {
    int n = blockIdx.x * blockDim.x + threadIdx.x;
    if (n >= BATCH * 24) return;
    int r = n / 24, m = n % 24;
    const float* src = O + (size_t)r * DOUT + m * 9;
    float X[9];
#pragma unroll
    for (int i = 0; i < 9; i++) X[i] = src[i];

    float C[9];
    cof3(X, C);
    float det0 = X[0]*C[0] + X[1]*C[1] + X[2]*C[2];
    float sgn = (det0 >= 0.f) ? 1.f : -1.f;

    float fro = 0.f;
#pragma unroll
    for (int i = 0; i < 9; i++) fro = fmaf(X[i], X[i], fro);
    float inv = rsqrtf(fmaxf(fro, 1e-30f));
#pragma unroll
    for (int i = 0; i < 9; i++) X[i] *= inv;

#pragma unroll
    for (int it = 0; it < 12; it++) {
        cof3(X, C);
        float det = X[0]*C[0] + X[1]*C[1] + X[2]*C[2];
        float adet = fabsf(det);
        if (adet < 1e-30f) break;
        float gscale = rcbrtf(adet);
        float invdet = 1.f / det;
        float ig = 0.5f * invdet / gscale;
        float hg = 0.5f * gscale;
#pragma unroll
        for (int i = 0; i < 9; i++) X[i] = hg * X[i] + ig * C[i];
    }

    float* dst = out + (size_t)n * 9;
#pragma unroll
    for (int i = 0; i < 9; i++) dst[i] = X[i] * sgn;
}

__global__ void betas_kernel(const float* __restrict__ O, float* __restrict__ out) {
    int i = blockIdx.x * blockDim.x + threadIdx.x;
    if (i >= BATCH * 10) return;
    int r = i / 10, j = i % 10;
    out[(size_t)BATCH * 216 + i] = O[(size_t)r * DOUT + 216 + j];
}

// ---------------------------------------------------------------------------
// Launch
// ---------------------------------------------------------------------------
extern "C" void kernel_launch(void* const* d_in, const int* in_sizes, int n_in,
                              void* d_out, int out_size)
{
    const float* V   = (const float*)d_in[0];
    const float* W0  = (const float*)d_in[1];
    const float* b0  = (const float*)d_in[2];
    const float* g0  = (const float*)d_in[3];
    const float* be0 = (const float*)d_in[4];
    const float* W1a = (const float*)d_in[5];
    const float* b1a = (const float*)d_in[6];
    const float* g1a = (const float*)d_in[7];
    const float* be1a= (const float*)d_in[8];
    const float* W1b = (const float*)d_in[9];
    const float* b1b = (const float*)d_in[10];
    const float* g1b = (const float*)d_in[11];
    const float* be1b= (const float*)d_in[12];
    const float* W2a = (const float*)d_in[13];
    const float* b2a = (const float*)d_in[14];
    const float* g2a = (const float*)d_in[15];
    const float* be2a= (const float*)d_in[16];
    const float* W2b = (const float*)d_in[17];
    const float* b2b = (const float*)d_in[18];
    const float* g2b = (const float*)d_in[19];
    const float* be2b= (const float*)d_in[20];
    const float* W3  = (const float*)d_in[21];
    const float* b3  = (const float*)d_in[22];

    float *Y, *H, *O;
    cudaGetSymbolAddress((void**)&Y, g_Y);
    cudaGetSymbolAddress((void**)&H, g_H);
    cudaGetSymbolAddress((void**)&O, g_O);

    __nv_bfloat16 *A0s[3], *Hs[3], *Ts[3];
    __nv_bfloat16 *W0p[3], *W1ap[3], *W1bp[3], *W2ap[3], *W2bp[3], *W3p[3];
    {
        __nv_bfloat16* base;
        cudaGetSymbolAddress((void**)&base, g_A01); A0s[0] = base;
        cudaGetSymbolAddress((void**)&base, g_A02); A0s[1] = base;
        cudaGetSymbolAddress((void**)&base, g_A03); A0s[2] = base;
        cudaGetSymbolAddress((void**)&base, g_H1);  Hs[0] = base;
        cudaGetSymbolAddress((void**)&base, g_H2);  Hs[1] = base;
        cudaGetSymbolAddress((void**)&base, g_H3);  Hs[2] = base;
        cudaGetSymbolAddress((void**)&base, g_T1);  Ts[0] = base;
        cudaGetSymbolAddress((void**)&base, g_T2);  Ts[1] = base;
        cudaGetSymbolAddress((void**)&base, g_T3);  Ts[2] = base;
        cudaGetSymbolAddress((void**)&base, g_W0s);
        W0p[0] = base; W0p[1] = base + (size_t)DH * DINP; W0p[2] = base + 2 * (size_t)DH * DINP;
        cudaGetSymbolAddress((void**)&base, g_W1as);
        W1ap[0] = base; W1ap[1] = base + (size_t)DH * DH; W1ap[2] = base + 2 * (size_t)DH * DH;
        cudaGetSymbolAddress((void**)&base, g_W1bs);
        W1bp[0] = base; W1bp[1] = base + (size_t)DH * DH; W1bp[2] = base + 2 * (size_t)DH * DH;
        cudaGetSymbolAddress((void**)&base, g_W2as);
        W2ap[0] = base; W2ap[1] = base + (size_t)DH * DH; W2ap[2] = base + 2 * (size_t)DH * DH;
        cudaGetSymbolAddress((void**)&base, g_W2bs);
        W2bp[0] = base; W2bp[1] = base + (size_t)DH * DH; W2bp[2] = base + 2 * (size_t)DH * DH;
        cudaGetSymbolAddress((void**)&base, g_W3s);
        W3p[0] = base; W3p[1] = base + (size_t)DOUTP * DH; W3p[2] = base + 2 * (size_t)DOUTP * DH;
    }

    cudaFuncSetAttribute(gemm_mma_split3, cudaFuncAttributeMaxDynamicSharedMemorySize, SMEM_REQ);

    // ---- prep: weight transpose+split, input split ----
    dim3 tb(32, 32);
    split_transpose<<<dim3(DINP / 32, DH / 32), tb>>>(W0, W0p[0], W0p[1], W0p[2], DIN, DH, DINP, DH);
    split_transpose<<<dim3(DH / 32, DH / 32), tb>>>(W1a, W1ap[0], W1ap[1], W1ap[2], DH, DH, DH, DH);
    split_transpose<<<dim3(DH / 32, DH / 32), tb>>>(W1b, W1bp[0], W1bp[1], W1bp[2], DH, DH, DH, DH);
    split_transpose<<<dim3(DH / 32, DH / 32), tb>>>(W2a, W2ap[0], W2ap[1], W2ap[2], DH, DH, DH, DH);
    split_transpose<<<dim3(DH / 32, DH / 32), tb>>>(W2b, W2bp[0], W2bp[1], W2bp[2], DH, DH, DH, DH);
    split_transpose<<<dim3(DH / 32, DOUTP / 32), tb>>>(W3, W3p[0], W3p[1], W3p[2], DH, DOUT, DH, DOUTP);
    {
        int total = BATCH * DINP;
        split_pad_rows<<<(total + 255) / 256, 256>>>(V, A0s[0], A0s[1], A0s[2], DIN, DINP, total);
    }

    const dim3 gGrid(DH / BN, BATCH / BM);       // (8, 64)
    const dim3 gGrid3(DOUTP / BN, BATCH / BM);   // (2, 64)
    const dim3 statGrid(32, 32), statBlk(32, 8);
    const int applyBlocks = (BATCH * DH / 4 + 255) / 256;

    auto bn_stats = [&](const float* g, const float* be) {
        zero_stats<<<1, DH>>>();
        colstats<<<statGrid, statBlk>>>(Y);
        finalize_bn<<<DH / 256, 256>>>(g, be);
    };

    // layer 0
    gemm_mma_split3<<<gGrid, NTHREADS, SMEM_REQ>>>(A0s[0], A0s[1], A0s[2],
                                                   W0p[0], W0p[1], W0p[2], b0, Y, DINP, DH, DH);
    bn_stats(g0, be0);
    apply_bn_split<<<applyBlocks, 256>>>((const float4*)Y, nullptr, (float4*)H,
                                         (uint2*)Hs[0], (uint2*)Hs[1], (uint2*)Hs[2], 0, 1);
    // block 1
    gemm_mma_split3<<<gGrid, NTHREADS, SMEM_REQ>>>(Hs[0], Hs[1], Hs[2],
                                                   W1ap[0], W1ap[1], W1ap[2], b1a, Y, DH, DH, DH);
    bn_stats(g1a, be1a);
    apply_bn_split<<<applyBlocks, 256>>>((const float4*)Y, nullptr, nullptr,
                                         (uint2*)Ts[0], (uint2*)Ts[1], (uint2*)Ts[2], 0, 0);
    gemm_mma_split3<<<gGrid, NTHREADS, SMEM_REQ>>>(Ts[0], Ts[1], Ts[2],
                                                   W1bp[0], W1bp[1], W1bp[2], b1b, Y, DH, DH, DH);
    bn_stats(g1b, be1b);
    apply_bn_split<<<applyBlocks, 256>>>((const float4*)Y, (const float4*)H, (float4*)H,
                                         (uint2*)Hs[0], (uint2*)Hs[1], (uint2*)Hs[2], 1, 1);
    // block 2
    gemm_mma_split3<<<gGrid, NTHREADS, SMEM_REQ>>>(Hs[0], Hs[1], Hs[2],
                                                   W2ap[0], W2ap[1], W2ap[2], b2a, Y, DH, DH, DH);
    bn_stats(g2a, be2a);
    apply_bn_split<<<applyBlocks, 256>>>((const float4*)Y, nullptr, nullptr,
                                         (uint2*)Ts[0], (uint2*)Ts[1], (uint2*)Ts[2], 0, 0);
    gemm_mma_split3<<<gGrid, NTHREADS, SMEM_REQ>>>(Ts[0], Ts[1], Ts[2],
                                                   W2bp[0], W2bp[1], W2bp[2], b2b, Y, DH, DH, DH);
    bn_stats(g2b, be2b);
    apply_bn_split<<<applyBlocks, 256>>>((const float4*)Y, (const float4*)H, (float4*)H,
                                         (uint2*)Hs[0], (uint2*)Hs[1], (uint2*)Hs[2], 1, 1);
    // head
    gemm_mma_split3<<<gGrid3, NTHREADS, SMEM_REQ>>>(Hs[0], Hs[1], Hs[2],
                                                    W3p[0], W3p[1], W3p[2], b3, O, DH, DOUT, DOUT);

    polar_kernel<<<(BATCH * 24 + 255) / 256, 256>>>(O, (float*)d_out);
    betas_kernel<<<(BATCH * 10 + 255) / 256, 256>>>(O, (float*)d_out);
}

// round 6
// speedup vs baseline: 3.0316x; 1.6745x over previous
#include <cuda_runtime.h>
#include <cuda_fp16.h>
#include <math.h>
#include <stdint.h>

// ---------------------------------------------------------------------------
// Problem constants
// ---------------------------------------------------------------------------
#define BATCH   8192
#define DIN     5169      // 1723*3
#define DINP    5184      // padded to 64
#define DH      1024
#define DOUT    226
#define DOUTP   256
#define EPS     1e-5f

// GEMM tiling: block 128x128, 512 threads (16 warps), warp tile 32x32
#define BM      128
#define BN      128
#define BK      64
#define NTHREADS 512
#define OFF_A1  0
#define OFF_A2  16384
#define OFF_B1  32768
#define OFF_B2  49152
#define STAGE   65536
#define SMEM_REQ (2*STAGE)

__device__ __forceinline__ uint32_t smem_u32(const void* p) {
    uint32_t a;
    asm("{ .reg .u64 t; cvta.to.shared.u64 t, %1; cvt.u32.u64 %0, t; }" : "=r"(a) : "l"(p));
    return a;
}

#define CPA16(dst, src) asm volatile("cp.async.cg.shared.global [%0], [%1], 16;" :: "r"(dst), "l"(src) : "memory")
#define CP_COMMIT() asm volatile("cp.async.commit_group;" ::: "memory")
#define CP_WAIT1()  asm volatile("cp.async.wait_group 1;" ::: "memory")
#define CP_WAIT0()  asm volatile("cp.async.wait_group 0;" ::: "memory")

#define LDSM4(r, addr) \
    asm volatile("ldmatrix.sync.aligned.m8n8.x4.shared.b16 {%0,%1,%2,%3}, [%4];" \
        : "=r"((r)[0]), "=r"((r)[1]), "=r"((r)[2]), "=r"((r)[3]) : "r"(addr))

#define MMA16816(c, a, b) \
    asm volatile("mma.sync.aligned.m16n8k16.row.col.f32.f16.f16.f32 " \
        "{%0,%1,%2,%3}, {%4,%5,%6,%7}, {%8,%9}, {%0,%1,%2,%3};" \
        : "+f"((c)[0]), "+f"((c)[1]), "+f"((c)[2]), "+f"((c)[3]) \
        : "r"((a)[0]), "r"((a)[1]), "r"((a)[2]), "r"((a)[3]), \
          "r"((b)[0]), "r"((b)[1]))

// ---------------------------------------------------------------------------
// Device scratch
// ---------------------------------------------------------------------------
__device__ float g_Y[BATCH * DH];
__device__ float g_H[BATCH * DH];
__device__ float g_O[BATCH * DOUT];
__device__ float g_sum[DH];
__device__ float g_sumsq[DH];
__device__ float g_a[DH];
__device__ float g_c[DH];

// 2-way fp16 splits for activations
__device__ __half g_A01[BATCH * DINP];
__device__ __half g_A02[BATCH * DINP];
__device__ __half g_H1[BATCH * DH];
__device__ __half g_H2[BATCH * DH];
__device__ __half g_T1[BATCH * DH];
__device__ __half g_T2[BATCH * DH];

// 2-way fp16 splits for weights (transposed [N][K])
__device__ __half g_W0s[2][DH * DINP];
__device__ __half g_W1as[2][DH * DH];
__device__ __half g_W1bs[2][DH * DH];
__device__ __half g_W2as[2][DH * DH];
__device__ __half g_W2bs[2][DH * DH];
__device__ __half g_W3s[2][DOUTP * DH];

// ---------------------------------------------------------------------------
// Prep: transpose+split weights  W[K][N] fp32 -> s1/s2 [Npad][Kpad] fp16
// ---------------------------------------------------------------------------
__global__ void split_transpose(const float* __restrict__ W,
                                __half* __restrict__ s1,
                                __half* __restrict__ s2,
                                int K, int N, int Kpad, int Npad)
{
    __shared__ float sh[32][33];
    int k0 = blockIdx.x * 32, n0 = blockIdx.y * 32;
    int tx = threadIdx.x, ty = threadIdx.y;
    int k = k0 + ty, n = n0 + tx;
    sh[ty][tx] = (k < K && n < N) ? W[(size_t)k * N + n] : 0.f;
    __syncthreads();
    int no = n0 + ty, ko = k0 + tx;
    if (no < Npad && ko < Kpad) {
        float v = sh[tx][ty];
        __half h1 = __float2half(v);
        float r1 = v - __half2float(h1);
        size_t idx = (size_t)no * Kpad + ko;
        s1[idx] = h1;
        s2[idx] = __float2half(r1);
    }
}

// Prep: split activations with K padding (row-major, no transpose)
__global__ void split_pad_rows(const float* __restrict__ src,
                               __half* __restrict__ s1,
                               __half* __restrict__ s2,
                               int cols, int colsPad, int total)
{
    int idx = blockIdx.x * blockDim.x + threadIdx.x;
    if (idx >= total) return;
    int r = idx / colsPad, c = idx - r * colsPad;
    float v = (c < cols) ? src[(size_t)r * cols + c] : 0.f;
    __half h1 = __float2half(v);
    s1[idx] = h1;
    s2[idx] = __float2half(v - __half2float(h1));
}

// ---------------------------------------------------------------------------
// mma.sync 2-split fp16 GEMM (fp32-accurate, split accumulators):
//   C[M][ldC] = A(M x Kpad) * B^T(Npad x Kpad) + bias
// main acc: a1b1.  corr acc: a2b1, a1b2.   (dropped a2b2 ~ 2^-22)
// Grid (Npad/BN, M/BM), 512 threads (16 warps), warp tile 32x32.
// ---------------------------------------------------------------------------
__device__ __forceinline__ void prefetch_stage(
    uint32_t s0,
    const __half* __restrict__ A1, const __half* __restrict__ A2,
    const __half* __restrict__ B1, const __half* __restrict__ B2,
    int row0, int col0, size_t Kpad, size_t kb, int tid)
{
#pragma unroll
    for (int i = 0; i < 2; i++) {
        int idx = i * NTHREADS + tid;
        int r = idx >> 3, c8 = idx & 7;
        uint32_t dst = (uint32_t)(r * 128 + ((c8 ^ (r & 7)) << 4));
        size_t g = (size_t)(row0 + r) * Kpad + kb + (size_t)c8 * 8;
        CPA16(s0 + OFF_A1 + dst, A1 + g);
        CPA16(s0 + OFF_A2 + dst, A2 + g);
    }
#pragma unroll
    for (int i = 0; i < 2; i++) {
        int idx = i * NTHREADS + tid;
        int r = idx >> 3, c8 = idx & 7;
        uint32_t dst = (uint32_t)(r * 128 + ((c8 ^ (r & 7)) << 4));
        size_t g = (size_t)(col0 + r) * Kpad + kb + (size_t)c8 * 8;
        CPA16(s0 + OFF_B1 + dst, B1 + g);
        CPA16(s0 + OFF_B2 + dst, B2 + g);
    }
    CP_COMMIT();
}

__global__ void __launch_bounds__(NTHREADS, 1) gemm_mma_split2(
    const __half* __restrict__ A1, const __half* __restrict__ A2,
    const __half* __restrict__ B1, const __half* __restrict__ B2,
    const float* __restrict__ bias, float* __restrict__ C,
    int Kpad, int Nreal, int ldC)
{
    extern __shared__ char smraw[];
    const uint32_t sb = smem_u32(smraw);

    const int tid = threadIdx.x, wid = tid >> 5, lane = tid & 31;
    const int row0 = blockIdx.y * BM;
    const int col0 = blockIdx.x * BN;
    const int wm = (wid >> 2) * 32;        // warp m-offset: 4 groups of 32
    const int wn = (wid & 3) * 32;         // warp n-offset: 4 groups of 32
    const int T = Kpad / BK;

    float am[2][4][4];     // main accumulator (a1*b1)
    float ac[2][4][4];     // correction accumulator (a2b1, a1b2)
#pragma unroll
    for (int i = 0; i < 2; i++)
#pragma unroll
        for (int j = 0; j < 4; j++)
#pragma unroll
            for (int v = 0; v < 4; v++) { am[i][j][v] = 0.f; ac[i][j][v] = 0.f; }

    const int la_r  = (lane & 7) + (lane & 8);            // A row within 16
    const int la_kh = (lane & 16) ? 8 : 0;                // A k-half
    const int lb_r  = (lane & 7) + ((lane & 16) ? 8 : 0); // B n-row within 16
    const int lb_kh = (lane & 8) ? 8 : 0;                 // B k-half

    prefetch_stage(sb, A1, A2, B1, B2, row0, col0, (size_t)Kpad, 0, tid);

    for (int t = 0; t < T; t++) {
        if (t + 1 < T) {
            prefetch_stage(sb + ((t + 1) & 1) * STAGE, A1, A2, B1, B2,
                           row0, col0, (size_t)Kpad, (size_t)(t + 1) * BK, tid);
            CP_WAIT1();
        } else {
            CP_WAIT0();
        }
        __syncthreads();

        const uint32_t s0 = sb + (t & 1) * STAGE;
#pragma unroll
        for (int ks = 0; ks < 4; ks++) {
            // A splits: 2 m-tiles x 2 splits = 4 LDSM4 (16 regs)
            uint32_t a1[2][4], a2[2][4];
#pragma unroll
            for (int i = 0; i < 2; i++) {
                int r = wm + 16 * i + la_r;
                int k = ks * 16 + la_kh;
                uint32_t addr = s0 + OFF_A1 + r * 128 + ((((k >> 3) ^ r) & 7) << 4);
                LDSM4(a1[i], addr);
                LDSM4(a2[i], addr + (OFF_A2 - OFF_A1));
            }
            const int rB = wn + lb_r;
            const int kB = ks * 16 + lb_kh;
            const uint32_t baddr0 = s0 + OFF_B1 + rB * 128 + ((((kB >> 3) ^ rB) & 7) << 4);
            const uint32_t baddr1 = s0 + OFF_B1 + (rB + 16) * 128 + ((((kB >> 3) ^ (rB + 16)) & 7) << 4);

            // ---- B split 1: a1b1 -> main; a2b1 -> corr ----
            {
                uint32_t b[4][2], q[4];
                LDSM4(q, baddr0);
                b[0][0]=q[0]; b[0][1]=q[1]; b[1][0]=q[2]; b[1][1]=q[3];
                LDSM4(q, baddr1);
                b[2][0]=q[0]; b[2][1]=q[1]; b[3][0]=q[2]; b[3][1]=q[3];
#pragma unroll
                for (int i = 0; i < 2; i++)
#pragma unroll
                    for (int j = 0; j < 4; j++) {
                        MMA16816(am[i][j], a1[i], b[j]);
                        MMA16816(ac[i][j], a2[i], b[j]);
                    }
            }
            // ---- B split 2: a1b2 -> corr ----
            {
                uint32_t b[4][2], q[4];
                LDSM4(q, baddr0 + (OFF_B2 - OFF_B1));
                b[0][0]=q[0]; b[0][1]=q[1]; b[1][0]=q[2]; b[1][1]=q[3];
                LDSM4(q, baddr1 + (OFF_B2 - OFF_B1));
                b[2][0]=q[0]; b[2][1]=q[1]; b[3][0]=q[2]; b[3][1]=q[3];
#pragma unroll
                for (int i = 0; i < 2; i++)
#pragma unroll
                    for (int j = 0; j < 4; j++)
                        MMA16816(ac[i][j], a1[i], b[j]);
            }
        }
        __syncthreads();
    }

    // epilogue: combine accumulators, add bias, store
    const int gid = lane >> 2, tig = lane & 3;
#pragma unroll
    for (int i = 0; i < 2; i++) {
        int r = row0 + wm + 16 * i + gid;
#pragma unroll
        for (int j = 0; j < 4; j++) {
            int cc = col0 + wn + 8 * j + tig * 2;
            if (cc < Nreal) {
                float b0 = bias[cc], b1 = bias[cc + 1];
                float2 v0 = make_float2(am[i][j][0] + ac[i][j][0] + b0,
                                        am[i][j][1] + ac[i][j][1] + b1);
                float2 v1 = make_float2(am[i][j][2] + ac[i][j][2] + b0,
                                        am[i][j][3] + ac[i][j][3] + b1);
                *reinterpret_cast<float2*>(C + (size_t)r * ldC + cc) = v0;
                *reinterpret_cast<float2*>(C + (size_t)(r + 8) * ldC + cc) = v1;
            }
        }
    }
}

// ---------------------------------------------------------------------------
// BN stats over batch
// ---------------------------------------------------------------------------
__global__ void zero_stats() {
    int i = threadIdx.x;
    g_sum[i] = 0.f;
    g_sumsq[i] = 0.f;
}

__global__ void colstats(const float* __restrict__ Y) {
    const int col = blockIdx.x * 32 + threadIdx.x;
    const int rowsPerBlock = BATCH / gridDim.y;
    const int r0 = blockIdx.y * rowsPerBlock;
    float s = 0.f, q = 0.f;
    for (int r = r0 + threadIdx.y; r < r0 + rowsPerBlock; r += 8) {
        float v = Y[(size_t)r * DH + col];
        s += v;
        q = fmaf(v, v, q);
    }
    __shared__ float ss[8][32];
    __shared__ float sq[8][32];
    ss[threadIdx.y][threadIdx.x] = s;
    sq[threadIdx.y][threadIdx.x] = q;
    __syncthreads();
    if (threadIdx.y == 0) {
        float S = 0.f, Q = 0.f;
#pragma unroll
        for (int i = 0; i < 8; i++) { S += ss[i][threadIdx.x]; Q += sq[i][threadIdx.x]; }
        atomicAdd(&g_sum[col], S);
        atomicAdd(&g_sumsq[col], Q);
    }
}

__global__ void finalize_bn(const float* __restrict__ g, const float* __restrict__ be) {
    int c = blockIdx.x * blockDim.x + threadIdx.x;
    if (c >= DH) return;
    const float invM = 1.f / (float)BATCH;
    float mean = g_sum[c] * invM;
    float var  = g_sumsq[c] * invM - mean * mean;
    float a = g[c] * rsqrtf(var + EPS);
    g_a[c] = a;
    g_c[c] = be[c] - a * mean;
}

// D = relu( res + a*Y + c ), write fp32 (optional) + 2-way fp16 splits
__global__ void apply_bn_split(const float4* __restrict__ Y4,
                               const float4* __restrict__ R4,
                               float4* __restrict__ H4,
                               uint2* __restrict__ o1,
                               uint2* __restrict__ o2,
                               int has_res, int write_f32)
{
    int i = blockIdx.x * blockDim.x + threadIdx.x;
    if (i >= BATCH * DH / 4) return;
    int c4 = i & 255;
    float4 a = reinterpret_cast<const float4*>(g_a)[c4];
    float4 c = reinterpret_cast<const float4*>(g_c)[c4];
    float4 y = Y4[i];
    float4 r = make_float4(0.f, 0.f, 0.f, 0.f);
    if (has_res) r = R4[i];
    float o[4];
    o[0] = fmaxf(0.f, fmaf(a.x, y.x, c.x) + r.x);
    o[1] = fmaxf(0.f, fmaf(a.y, y.y, c.y) + r.y);
    o[2] = fmaxf(0.f, fmaf(a.z, y.z, c.z) + r.z);
    o[3] = fmaxf(0.f, fmaf(a.w, y.w, c.w) + r.w);
    if (write_f32) H4[i] = make_float4(o[0], o[1], o[2], o[3]);

    union { __half h[4]; uint2 u; } p1, p2;
#pragma unroll
    for (int v = 0; v < 4; v++) {
        __half h1 = __float2half(o[v]);
        p1.h[v] = h1;
        p2.h[v] = __float2half(o[v] - __half2float(h1));
    }
    o1[i] = p1.u;
    o2[i] = p2.u;
}

// ---------------------------------------------------------------------------
// Polar decomposition of 3x3 (== U*Vh), times sign(det)
// ---------------------------------------------------------------------------
__device__ __forceinline__ void cof3(const float* X, float* C) {
    C[0] = X[4]*X[8] - X[5]*X[7];
    C[1] = X[5]*X[6] - X[3]*X[8];
    C[2] = X[3]*X[7] - X[4]*X[6];
    C[3] = X[2]*X[7] - X[1]*X[8];
    C[4] = X[0]*X[8] - X[2]*X[6];
    C[5] = X[1]*X[6] - X[0]*X[7];
    C[6] = X[1]*X[5] - X[2]*X[4];
    C[7] = X[2]*X[3] - X[0]*X[5];
    C[8] = X[0]*X[4] - X[1]*X[3];
}

__global__ void polar_kernel(const float* __restrict__ O, float* __restrict__ out) {
    int n = blockIdx.x * blockDim.x + threadIdx.x;
    if (n >= BATCH * 24) return;
    int r = n / 24, m = n % 24;
    const float* src = O + (size_t)r * DOUT + m * 9;
    float X[9];
#pragma unroll
    for (int i = 0; i < 9; i++) X[i] = src[i];

    float C[9];
    cof3(X, C);
    float det0 = X[0]*C[0] + X[1]*C[1] + X[2]*C[2];
    float sgn = (det0 >= 0.f) ? 1.f : -1.f;

    float fro = 0.f;
#pragma unroll
    for (int i = 0; i < 9; i++) fro = fmaf(X[i], X[i], fro);
    float inv = rsqrtf(fmaxf(fro, 1e-30f));
#pragma unroll
    for (int i = 0; i < 9; i++) X[i] *= inv;

#pragma unroll
    for (int it = 0; it < 12; it++) {
        cof3(X, C);
        float det = X[0]*C[0] + X[1]*C[1] + X[2]*C[2];
        float adet = fabsf(det);
        if (adet < 1e-30f) break;
        float gscale = rcbrtf(adet);
        float invdet = 1.f / det;
        float ig = 0.5f * invdet / gscale;
        float hg = 0.5f * gscale;
#pragma unroll
        for (int i = 0; i < 9; i++) X[i] = hg * X[i] + ig * C[i];
    }

    float* dst = out + (size_t)n * 9;
#pragma unroll
    for (int i = 0; i < 9; i++) dst[i] = X[i] * sgn;
}

__global__ void betas_kernel(const float* __restrict__ O, float* __restrict__ out) {
    int i = blockIdx.x * blockDim.x + threadIdx.x;
    if (i >= BATCH * 10) return;
    int r = i / 10, j = i % 10;
    out[(size_t)BATCH * 216 + i] = O[(size_t)r * DOUT + 216 + j];
}

// ---------------------------------------------------------------------------
// Launch
// ---------------------------------------------------------------------------
extern "C" void kernel_launch(void* const* d_in, const int* in_sizes, int n_in,
                              void* d_out, int out_size)
{
    const float* V   = (const float*)d_in[0];
    const float* W0  = (const float*)d_in[1];
    const float* b0  = (const float*)d_in[2];
    const float* g0  = (const float*)d_in[3];
    const float* be0 = (const float*)d_in[4];
    const float* W1a = (const float*)d_in[5];
    const float* b1a = (const float*)d_in[6];
    const float* g1a = (const float*)d_in[7];
    const float* be1a= (const float*)d_in[8];
    const float* W1b = (const float*)d_in[9];
    const float* b1b = (const float*)d_in[10];
    const float* g1b = (const float*)d_in[11];
    const float* be1b= (const float*)d_in[12];
    const float* W2a = (const float*)d_in[13];
    const float* b2a = (const float*)d_in[14];
    const float* g2a = (const float*)d_in[15];
    const float* be2a= (const float*)d_in[16];
    const float* W2b = (const float*)d_in[17];
    const float* b2b = (const float*)d_in[18];
    const float* g2b = (const float*)d_in[19];
    const float* be2b= (const float*)d_in[20];
    const float* W3  = (const float*)d_in[21];
    const float* b3  = (const float*)d_in[22];

    float *Y, *H, *O;
    cudaGetSymbolAddress((void**)&Y, g_Y);
    cudaGetSymbolAddress((void**)&H, g_H);
    cudaGetSymbolAddress((void**)&O, g_O);

    __half *A0s[2], *Hs[2], *Ts[2];
    __half *W0p[2], *W1ap[2], *W1bp[2], *W2ap[2], *W2bp[2], *W3p[2];
    {
        __half* base;
        cudaGetSymbolAddress((void**)&base, g_A01); A0s[0] = base;
        cudaGetSymbolAddress((void**)&base, g_A02); A0s[1] = base;
        cudaGetSymbolAddress((void**)&base, g_H1);  Hs[0] = base;
        cudaGetSymbolAddress((void**)&base, g_H2);  Hs[1] = base;
        cudaGetSymbolAddress((void**)&base, g_T1);  Ts[0] = base;
        cudaGetSymbolAddress((void**)&base, g_T2);  Ts[1] = base;
        cudaGetSymbolAddress((void**)&base, g_W0s);
        W0p[0] = base; W0p[1] = base + (size_t)DH * DINP;
        cudaGetSymbolAddress((void**)&base, g_W1as);
        W1ap[0] = base; W1ap[1] = base + (size_t)DH * DH;
        cudaGetSymbolAddress((void**)&base, g_W1bs);
        W1bp[0] = base; W1bp[1] = base + (size_t)DH * DH;
        cudaGetSymbolAddress((void**)&base, g_W2as);
        W2ap[0] = base; W2ap[1] = base + (size_t)DH * DH;
        cudaGetSymbolAddress((void**)&base, g_W2bs);
        W2bp[0] = base; W2bp[1] = base + (size_t)DH * DH;
        cudaGetSymbolAddress((void**)&base, g_W3s);
        W3p[0] = base; W3p[1] = base + (size_t)DOUTP * DH;
    }

    cudaFuncSetAttribute(gemm_mma_split2, cudaFuncAttributeMaxDynamicSharedMemorySize, SMEM_REQ);

    // ---- prep: weight transpose+split, input split ----
    dim3 tb(32, 32);
    split_transpose<<<dim3(DINP / 32, DH / 32), tb>>>(W0, W0p[0], W0p[1], DIN, DH, DINP, DH);
    split_transpose<<<dim3(DH / 32, DH / 32), tb>>>(W1a, W1ap[0], W1ap[1], DH, DH, DH, DH);
    split_transpose<<<dim3(DH / 32, DH / 32), tb>>>(W1b, W1bp[0], W1bp[1], DH, DH, DH, DH);
    split_transpose<<<dim3(DH / 32, DH / 32), tb>>>(W2a, W2ap[0], W2ap[1], DH, DH, DH, DH);
    split_transpose<<<dim3(DH / 32, DH / 32), tb>>>(W2b, W2bp[0], W2bp[1], DH, DH, DH, DH);
    split_transpose<<<dim3(DH / 32, DOUTP / 32), tb>>>(W3, W3p[0], W3p[1], DH, DOUT, DH, DOUTP);
    {
        int total = BATCH * DINP;
        split_pad_rows<<<(total + 255) / 256, 256>>>(V, A0s[0], A0s[1], DIN, DINP, total);
    }

    const dim3 gGrid(DH / BN, BATCH / BM);       // (8, 64)
    const dim3 gGrid3(DOUTP / BN, BATCH / BM);   // (2, 64)
    const dim3 statGrid(32, 32), statBlk(32, 8);
    const int applyBlocks = (BATCH * DH / 4 + 255) / 256;

    auto bn_stats = [&](const float* g, const float* be) {
        zero_stats<<<1, DH>>>();
        colstats<<<statGrid, statBlk>>>(Y);
        finalize_bn<<<DH / 256, 256>>>(g, be);
    };

    // layer 0
    gemm_mma_split2<<<gGrid, NTHREADS, SMEM_REQ>>>(A0s[0], A0s[1],
                                                   W0p[0], W0p[1], b0, Y, DINP, DH, DH);
    bn_stats(g0, be0);
    apply_bn_split<<<applyBlocks, 256>>>((const float4*)Y, nullptr, (float4*)H,
                                         (uint2*)Hs[0], (uint2*)Hs[1], 0, 1);
    // block 1
    gemm_mma_split2<<<gGrid, NTHREADS, SMEM_REQ>>>(Hs[0], Hs[1],
                                                   W1ap[0], W1ap[1], b1a, Y, DH, DH, DH);
    bn_stats(g1a, be1a);
    apply_bn_split<<<applyBlocks, 256>>>((const float4*)Y, nullptr, nullptr,
                                         (uint2*)Ts[0], (uint2*)Ts[1], 0, 0);
    gemm_mma_split2<<<gGrid, NTHREADS, SMEM_REQ>>>(Ts[0], Ts[1],
                                                   W1bp[0], W1bp[1], b1b, Y, DH, DH, DH);
    bn_stats(g1b, be1b);
    apply_bn_split<<<applyBlocks, 256>>>((const float4*)Y, (const float4*)H, (float4*)H,
                                         (uint2*)Hs[0], (uint2*)Hs[1], 1, 1);
    // block 2
    gemm_mma_split2<<<gGrid, NTHREADS, SMEM_REQ>>>(Hs[0], Hs[1],
                                                   W2ap[0], W2ap[1], b2a, Y, DH, DH, DH);
    bn_stats(g2a, be2a);
    apply_bn_split<<<applyBlocks, 256>>>((const float4*)Y, nullptr, nullptr,
                                         (uint2*)Ts[0], (uint2*)Ts[1], 0, 0);
    gemm_mma_split2<<<gGrid, NTHREADS, SMEM_REQ>>>(Ts[0], Ts[1],
                                                   W2bp[0], W2bp[1], b2b, Y, DH, DH, DH);
    bn_stats(g2b, be2b);
    apply_bn_split<<<applyBlocks, 256>>>((const float4*)Y, (const float4*)H, (float4*)H,
                                         (uint2*)Hs[0], (uint2*)Hs[1], 1, 1);
    // head
    gemm_mma_split2<<<gGrid3, NTHREADS, SMEM_REQ>>>(Hs[0], Hs[1],
                                                    W3p[0], W3p[1], b3, O, DH, DOUT, DOUT);

    polar_kernel<<<(BATCH * 24 + 255) / 256, 256>>>(O, (float*)d_out);
    betas_kernel<<<(BATCH * 10 + 255) / 256, 256>>>(O, (float*)d_out);
}